// round 8
// baseline (speedup 1.0000x reference)
#include <cstdint>
#include <cuda_runtime.h>
#include <cuda_bf16.h>
#include <mma.h>

using namespace nvcuda;

// ---------------- problem constants (fixed shapes) ----------------
#define NN 50000      // nodes
#define NN_PAD 50048  // padded to 391*128 for wmma tiles
#define NE 800000     // edges
#define DIN 128       // input feature dim
#define DH  256       // hidden dim (H1)
#define H2D 128       // readout hidden dim
#define NG  256       // num graphs

// ---------------- device scratch (static, allocation-free) ----------------
__device__ int   g_deg[NN];
__device__ int   g_rowptr[NN + 1];
__device__ int   g_cursor[NN];
__device__ int   g_col[NE];
__device__ float g_a1[(size_t)NN_PAD * DIN];   // mean-agg of input h (tf32-rounded)
__device__ float g_h1[(size_t)NN_PAD * DH];    // relu(a1@W1+b1)
__device__ float g_a2[(size_t)NN_PAD * DH];    // mean-agg of h1 (tf32-rounded)
__device__ float g_w1r[DIN * DH];              // tf32-rounded W1
__device__ float g_w2r[DH * DH];               // tf32-rounded W2
__device__ float g_wc[DH];                     // Wr1 @ Wr2  [256]
__device__ float g_gsum[NG];                   // per-graph partial sums
__device__ float g_c0;                         // br1.Wr2 + br2

// ---------------- helpers ----------------
__device__ __forceinline__ float tf32r(float x) {
    asm("cvt.rna.tf32.f32 %0, %0;" : "+f"(x));
    return x;
}
__device__ __forceinline__ void cp_async16(void* smem, const void* gmem) {
    unsigned int s = (unsigned int)__cvta_generic_to_shared(smem);
    asm volatile("cp.async.cg.shared.global [%0], [%1], 16;\n" :: "r"(s), "l"(gmem));
}
__device__ __forceinline__ void cp_commit() {
    asm volatile("cp.async.commit_group;\n");
}
__device__ __forceinline__ void cp_wait1() {
    asm volatile("cp.async.wait_group 1;\n");
}
__device__ __forceinline__ void cp_wait0() {
    asm volatile("cp.async.wait_group 0;\n");
}

// ---------------- CSR build ----------------
__global__ void zero_deg_kernel(int n) {
    int i = blockIdx.x * blockDim.x + threadIdx.x;
    if (i < n) g_deg[i] = 0;
}

__global__ void hist_kernel(const int* __restrict__ dst, int e) {
    int i = blockIdx.x * blockDim.x + threadIdx.x;
    if (i < e) atomicAdd(&g_deg[dst[i]], 1);
}

__global__ void scan_kernel(int n) {
    __shared__ int sums[1024];
    const int t = threadIdx.x;
    const int C = (n + 1023) / 1024;
    const int start = t * C;
    const int end = min(start + C, n);

    int local = 0;
    for (int i = start; i < end; i++) local += g_deg[i];
    sums[t] = local;
    __syncthreads();

    for (int off = 1; off < 1024; off <<= 1) {
        int v = (t >= off) ? sums[t - off] : 0;
        __syncthreads();
        sums[t] += v;
        __syncthreads();
    }

    int run = sums[t] - local;
    for (int i = start; i < end; i++) {
        g_rowptr[i] = run;
        g_cursor[i] = run;
        run += g_deg[i];
    }
    if (start < n && end == n) g_rowptr[n] = run;
}

__global__ void fill_kernel(const int* __restrict__ src, const int* __restrict__ dst, int e) {
    int i = blockIdx.x * blockDim.x + threadIdx.x;
    if (i < e) {
        int pos = atomicAdd(&g_cursor[dst[i]], 1);
        g_col[pos] = src[i];
    }
}

// ---------------- weight tf32 pre-round (float4) ----------------
__global__ void round_w_kernel(const float4* __restrict__ w, float4* __restrict__ out, int n4) {
    int i = blockIdx.x * blockDim.x + threadIdx.x;
    if (i < n4) {
        float4 v = w[i];
        v.x = tf32r(v.x); v.y = tf32r(v.y); v.z = tf32r(v.z); v.w = tf32r(v.w);
        out[i] = v;
    }
}

// ---------------- head collapse: wc = Wr1@Wr2, c0 = br1.Wr2 + br2 ----------------
// Also zeroes g_gsum (must run before the fused GEMM2).
__global__ void wc_kernel(const float* __restrict__ Wr1, const float* __restrict__ br1,
                          const float* __restrict__ Wr2, const float* __restrict__ br2) {
    const int t = threadIdx.x;  // 256
    float acc = 0.f;
    for (int j = 0; j < H2D; j++) acc += Wr1[t * H2D + j] * Wr2[j];
    g_wc[t] = acc;
    g_gsum[t] = 0.f;
    __shared__ float red[H2D];
    if (t < H2D) red[t] = br1[t] * Wr2[t];
    __syncthreads();
    for (int s = H2D / 2; s > 0; s >>= 1) {
        if (t < s) red[t] += red[t + s];
        __syncthreads();
    }
    if (t == 0) g_c0 = red[0] + br2[0];
}

// ---------------- mean aggregation (gather over CSR) ----------------
// WPN warps per node; each warp owns 128 contiguous floats of the row.
// Pure gather + mean; output tf32-rounded (feeds tf32 GEMM).
template <int D, int WPN>
__global__ void agg_kernel(const float* __restrict__ in, float* __restrict__ out) {
    const int gw = (blockIdx.x * blockDim.x + threadIdx.x) >> 5;
    const int node = gw / WPN;
    if (node >= NN) return;
    const int part = gw % WPN;
    const int lane = threadIdx.x & 31;
    const int fi = part * 32 + lane;        // float4 index within row
    constexpr int S4 = D / 4;               // row stride in float4

    const int s = g_rowptr[node];
    const int e = g_rowptr[node + 1];
    const float4* base = (const float4*)in;

    float4 acc = make_float4(0.f, 0.f, 0.f, 0.f);
    int j = s;
    for (; j + 3 < e; j += 4) {
        const int i0 = g_col[j], i1 = g_col[j + 1], i2 = g_col[j + 2], i3 = g_col[j + 3];
        float4 x0 = __ldg(&base[(size_t)i0 * S4 + fi]);
        float4 x1 = __ldg(&base[(size_t)i1 * S4 + fi]);
        float4 x2 = __ldg(&base[(size_t)i2 * S4 + fi]);
        float4 x3 = __ldg(&base[(size_t)i3 * S4 + fi]);
        acc.x += (x0.x + x1.x) + (x2.x + x3.x);
        acc.y += (x0.y + x1.y) + (x2.y + x3.y);
        acc.z += (x0.z + x1.z) + (x2.z + x3.z);
        acc.w += (x0.w + x1.w) + (x2.w + x3.w);
    }
    for (; j < e; j++) {
        const int i0 = g_col[j];
        float4 x0 = __ldg(&base[(size_t)i0 * S4 + fi]);
        acc.x += x0.x; acc.y += x0.y; acc.z += x0.z; acc.w += x0.w;
    }

    const float inv = 1.f / fmaxf((float)(e - s), 1.f);
    float4 o;
    o.x = tf32r(acc.x * inv);
    o.y = tf32r(acc.y * inv);
    o.z = tf32r(acc.z * inv);
    o.w = tf32r(acc.w * inv);
    ((float4*)out)[(size_t)node * S4 + fi] = o;
}

// ---------------- TF32 tensor-core GEMM (double-buffered cp.async) ----------------
// C[M,256] = A[M,K] @ B[K,256]; A,B pre-rounded tf32; M multiple of 128.
// EPI=1: C = relu(AB + bias), float4 stores (staged via smem).
// EPI=2: fused readout — per-row dot of relu(AB + bias) with g_wc, atomicAdd
//        into g_gsum[gid[row]]; nothing written to C.
template <int K, int EPI>
__global__ __launch_bounds__(256, 2)
void gemm_tf32_kernel(const float* __restrict__ A,
                      const float* __restrict__ B,
                      float* __restrict__ C,
                      const float* __restrict__ bias,
                      const int* __restrict__ gid) {
    constexpr int BM = 128, BN = 128, BK = 32;
    constexpr int LDA = BK + 4;    // 36
    constexpr int LDB = BN + 4;    // 132
    constexpr int LDC = BN + 4;    // 132 (epilogue staging)
    constexpr int NT = K / BK;
    constexpr int NB = 256;        // B/C row stride (DH)
    __shared__ __align__(16) float sbuf[2 * BM * LDA + 2 * BK * LDB];  // 70656 B
    float (*As)[BM][LDA] = reinterpret_cast<float(*)[BM][LDA]>(sbuf);
    float (*Bs)[BK][LDB] = reinterpret_cast<float(*)[BK][LDB]>(sbuf + 2 * BM * LDA);

    const int tid = threadIdx.x;
    const int warpId = tid >> 5;
    const int lane = tid & 31;
    const int warpRow = warpId >> 2;   // 0..1
    const int warpCol = warpId & 3;    // 0..3
    const int rowBase = blockIdx.y * BM;
    const int colBase = blockIdx.x * BN;

    const int aR = tid >> 3;           // 0..31 (+l*32)
    const int aC = (tid & 7) * 4;      // 0..28
    const int bR = tid >> 5;           // 0..7 (+l*8)
    const int bC = (tid & 31) * 4;     // 0..124

    auto load_tile = [&](int k0, int buf) {
#pragma unroll
        for (int l = 0; l < 4; l++) {
            int r = l * 32 + aR;
            cp_async16(&As[buf][r][aC], &A[(size_t)(rowBase + r) * K + k0 + aC]);
        }
#pragma unroll
        for (int l = 0; l < 4; l++) {
            int r = l * 8 + bR;
            cp_async16(&Bs[buf][r][bC], &B[(size_t)(k0 + r) * NB + colBase + bC]);
        }
        cp_commit();
    };

    wmma::fragment<wmma::accumulator, 16, 16, 8, float> acc[4][2];
#pragma unroll
    for (int i = 0; i < 4; i++)
#pragma unroll
        for (int j = 0; j < 2; j++) wmma::fill_fragment(acc[i][j], 0.f);

    load_tile(0, 0);

#pragma unroll
    for (int t = 0; t < NT; t++) {
        const int cur = t & 1;
        if (t + 1 < NT) {
            load_tile((t + 1) * BK, cur ^ 1);
            cp_wait1();
        } else {
            cp_wait0();
        }
        __syncthreads();

#pragma unroll
        for (int kk = 0; kk < BK; kk += 8) {
            wmma::fragment<wmma::matrix_a, 16, 16, 8, wmma::precision::tf32, wmma::row_major> a[4];
            wmma::fragment<wmma::matrix_b, 16, 16, 8, wmma::precision::tf32, wmma::row_major> b[2];
#pragma unroll
            for (int i = 0; i < 4; i++)
                wmma::load_matrix_sync(a[i], &As[cur][warpRow * 64 + i * 16][kk], LDA);
#pragma unroll
            for (int j = 0; j < 2; j++)
                wmma::load_matrix_sync(b[j], &Bs[cur][kk][warpCol * 32 + j * 16], LDB);
#pragma unroll
            for (int i = 0; i < 4; i++)
#pragma unroll
                for (int j = 0; j < 2; j++)
                    wmma::mma_sync(acc[i][j], a[i], b[j], acc[i][j]);
        }
        __syncthreads();
    }

    // ---- epilogue: stage C tile in smem (reuse pipeline buffers) ----
    float* Cs = sbuf;  // needs 128*132 = 16896 floats <= 17664 available
#pragma unroll
    for (int i = 0; i < 4; i++)
#pragma unroll
        for (int j = 0; j < 2; j++) {
            int r = warpRow * 64 + i * 16;
            int c = warpCol * 32 + j * 16;
            wmma::store_matrix_sync(&Cs[r * LDC + c], acc[i][j], LDC, wmma::mem_row_major);
        }
    __syncthreads();

    const int c4 = lane * 4;  // this lane's 4 columns within the tile
    float4 bv = *(const float4*)&bias[colBase + c4];

    if (EPI == 1) {
        // relu(x + bias) -> gmem, one row per warp iteration
#pragma unroll
        for (int rr = 0; rr < 16; rr++) {
            const int r = warpId * 16 + rr;
            float4 v = *(const float4*)&Cs[r * LDC + c4];
            v.x = fmaxf(v.x + bv.x, 0.f);
            v.y = fmaxf(v.y + bv.y, 0.f);
            v.z = fmaxf(v.z + bv.z, 0.f);
            v.w = fmaxf(v.w + bv.w, 0.f);
            *(float4*)&C[(size_t)(rowBase + r) * NB + colBase + c4] = v;
        }
    } else {
        // fused readout: per-row partial dot with wc, atomic into graph sums
        float4 wv = *(const float4*)&g_wc[colBase + c4];
#pragma unroll
        for (int rr = 0; rr < 16; rr++) {
            const int r = warpId * 16 + rr;
            float4 v = *(const float4*)&Cs[r * LDC + c4];
            float d = fmaxf(v.x + bv.x, 0.f) * wv.x
                    + fmaxf(v.y + bv.y, 0.f) * wv.y
                    + fmaxf(v.z + bv.z, 0.f) * wv.z
                    + fmaxf(v.w + bv.w, 0.f) * wv.w;
#pragma unroll
            for (int off = 16; off > 0; off >>= 1)
                d += __shfl_xor_sync(0xffffffffu, d, off);
            const int row = rowBase + r;
            if (lane == 0 && row < NN) atomicAdd(&g_gsum[gid[row]], d);
        }
    }
}

// ---------------- finalize: out[g] = gsum[g]/cnt_g + c0 ----------------
__global__ void finalize_kernel(const int* __restrict__ gid, int n, float* __restrict__ out) {
    const int g = threadIdx.x;  // 256
    int lo = 0, hi = n;
    while (lo < hi) { int m = (lo + hi) >> 1; if (gid[m] < g) lo = m + 1; else hi = m; }
    const int a = lo;
    hi = n;
    while (lo < hi) { int m = (lo + hi) >> 1; if (gid[m] <= g) lo = m + 1; else hi = m; }
    const float cnt = (float)(lo - a);
    out[g] = g_gsum[g] / fmaxf(cnt, 1.f) + g_c0;
}

// ---------------- launch ----------------
extern "C" void kernel_launch(void* const* d_in, const int* in_sizes, int n_in,
                              void* d_out, int out_size) {
    const float* h   = (const float*)d_in[0];
    const int*   src = (const int*)d_in[1];
    const int*   dst = (const int*)d_in[2];
    const int*   gid = (const int*)d_in[3];
    const float* W1  = (const float*)d_in[4];
    const float* b1  = (const float*)d_in[5];
    const float* W2  = (const float*)d_in[6];
    const float* b2  = (const float*)d_in[7];
    const float* Wr1 = (const float*)d_in[8];
    const float* br1 = (const float*)d_in[9];
    const float* Wr2 = (const float*)d_in[10];
    const float* br2 = (const float*)d_in[11];
    float* out = (float*)d_out;

    const int N = in_sizes[0] / DIN;   // 50000
    const int E = in_sizes[1];         // 800000

    float *pa1, *ph1, *pa2, *pw1, *pw2;
    cudaGetSymbolAddress((void**)&pa1, g_a1);
    cudaGetSymbolAddress((void**)&ph1, g_h1);
    cudaGetSymbolAddress((void**)&pa2, g_a2);
    cudaGetSymbolAddress((void**)&pw1, g_w1r);
    cudaGetSymbolAddress((void**)&pw2, g_w2r);

    // 1) CSR build + weight prep + head collapse
    zero_deg_kernel<<<(N + 255) / 256, 256>>>(N);
    hist_kernel<<<(E + 255) / 256, 256>>>(dst, E);
    wc_kernel<<<1, 256>>>(Wr1, br1, Wr2, br2);
    round_w_kernel<<<(DIN * DH / 4 + 255) / 256, 256>>>((const float4*)W1, (float4*)pw1, DIN * DH / 4);
    round_w_kernel<<<(DH * DH / 4 + 255) / 256, 256>>>((const float4*)W2, (float4*)pw2, DH * DH / 4);
    scan_kernel<<<1, 1024>>>(N);
    fill_kernel<<<(E + 255) / 256, 256>>>(src, dst, E);

    // 2) layer 1: mean-agg -> tf32 GEMM with fused relu+b1 epilogue
    agg_kernel<DIN, 1><<<(NN * 32 + 255) / 256, 256>>>(h, pa1);
    {
        dim3 grid(DH / 128, NN_PAD / 128);
        gemm_tf32_kernel<DIN, 1><<<grid, 256>>>(pa1, pw1, ph1, b1, nullptr);
    }

    // 3) layer 2: mean-agg -> tf32 GEMM with fused relu+b2+readout epilogue
    agg_kernel<DH, 2><<<(NN * 2 * 32 + 255) / 256, 256>>>(ph1, pa2);
    {
        dim3 grid(DH / 128, NN_PAD / 128);
        gemm_tf32_kernel<DH, 2><<<grid, 256>>>(pa2, pw2, nullptr, b2, gid);
    }

    // 4) finalize per-graph means + collapsed MLP head
    finalize_kernel<<<1, 256>>>(gid, N, out);
}

// round 9
// speedup vs baseline: 1.4183x; 1.4183x over previous
#include <cstdint>
#include <cuda_runtime.h>
#include <cuda_bf16.h>
#include <mma.h>

using namespace nvcuda;

// ---------------- problem constants (fixed shapes) ----------------
#define NN 50000      // nodes
#define NN_PAD 50048  // padded to 391*128 for wmma tiles
#define NE 800000     // edges
#define DIN 128       // input feature dim
#define DH  256       // hidden dim (H1)
#define H2D 128       // readout hidden dim
#define NG  256       // num graphs

// ---------------- device scratch (static, allocation-free) ----------------
__device__ int   g_deg[NN];
__device__ int   g_rowptr[NN + 1];
__device__ int   g_cursor[NN];
__device__ int   g_col[NE];
__device__ float g_a1[(size_t)NN_PAD * DIN];   // mean-agg of input h (tf32-rounded)
__device__ float g_h1[(size_t)NN_PAD * DH];    // a1@W1 (raw fp32)
__device__ float g_a2[(size_t)NN_PAD * DH];    // mean-agg of relu(h1+b1) (tf32-rounded)
__device__ float g_h2[(size_t)NN_PAD * DH];    // a2@W2 (raw fp32)
__device__ float g_w1r[DIN * DH];              // tf32-rounded W1
__device__ float g_w2r[DH * DH];               // tf32-rounded W2
__device__ float g_wc[DH];                     // Wr1 @ Wr2  [256]
__device__ float g_gsum[NG];                   // per-graph partial dot sums
__device__ float g_c0;                         // br1.Wr2 + br2

// ---------------- helpers ----------------
__device__ __forceinline__ float tf32r(float x) {
    asm("cvt.rna.tf32.f32 %0, %0;" : "+f"(x));
    return x;
}
__device__ __forceinline__ void cp_async16(void* smem, const void* gmem) {
    unsigned int s = (unsigned int)__cvta_generic_to_shared(smem);
    asm volatile("cp.async.cg.shared.global [%0], [%1], 16;\n" :: "r"(s), "l"(gmem));
}
__device__ __forceinline__ void cp_commit() {
    asm volatile("cp.async.commit_group;\n");
}
__device__ __forceinline__ void cp_wait1() {
    asm volatile("cp.async.wait_group 1;\n");
}
__device__ __forceinline__ void cp_wait0() {
    asm volatile("cp.async.wait_group 0;\n");
}

// ---------------- CSR build ----------------
__global__ void zero_deg_kernel(int n) {
    int i = blockIdx.x * blockDim.x + threadIdx.x;
    if (i < n) g_deg[i] = 0;
}

__global__ void hist_kernel(const int* __restrict__ dst, int e) {
    int i = blockIdx.x * blockDim.x + threadIdx.x;
    if (i < e) atomicAdd(&g_deg[dst[i]], 1);
}

__global__ void scan_kernel(int n) {
    __shared__ int sums[1024];
    const int t = threadIdx.x;
    const int C = (n + 1023) / 1024;
    const int start = t * C;
    const int end = min(start + C, n);

    int local = 0;
    for (int i = start; i < end; i++) local += g_deg[i];
    sums[t] = local;
    __syncthreads();

    for (int off = 1; off < 1024; off <<= 1) {
        int v = (t >= off) ? sums[t - off] : 0;
        __syncthreads();
        sums[t] += v;
        __syncthreads();
    }

    int run = sums[t] - local;
    for (int i = start; i < end; i++) {
        g_rowptr[i] = run;
        g_cursor[i] = run;
        run += g_deg[i];
    }
    if (start < n && end == n) g_rowptr[n] = run;
}

__global__ void fill_kernel(const int* __restrict__ src, const int* __restrict__ dst, int e) {
    int i = blockIdx.x * blockDim.x + threadIdx.x;
    if (i < e) {
        int pos = atomicAdd(&g_cursor[dst[i]], 1);
        g_col[pos] = src[i];
    }
}

// ---------------- weight tf32 pre-round (float4) ----------------
__global__ void round_w_kernel(const float4* __restrict__ w, float4* __restrict__ out, int n4) {
    int i = blockIdx.x * blockDim.x + threadIdx.x;
    if (i < n4) {
        float4 v = w[i];
        v.x = tf32r(v.x); v.y = tf32r(v.y); v.z = tf32r(v.z); v.w = tf32r(v.w);
        out[i] = v;
    }
}

// ---------------- head collapse: wc = Wr1@Wr2, c0 = br1.Wr2 + br2 ----------------
// Also zeroes g_gsum (must run before dot_readout).
__global__ void wc_kernel(const float* __restrict__ Wr1, const float* __restrict__ br1,
                          const float* __restrict__ Wr2, const float* __restrict__ br2) {
    const int t = threadIdx.x;  // 256
    float acc = 0.f;
    for (int j = 0; j < H2D; j++) acc += Wr1[t * H2D + j] * Wr2[j];
    g_wc[t] = acc;
    g_gsum[t] = 0.f;
    __shared__ float red[H2D];
    if (t < H2D) red[t] = br1[t] * Wr2[t];
    __syncthreads();
    for (int s = H2D / 2; s > 0; s >>= 1) {
        if (t < s) red[t] += red[t + s];
        __syncthreads();
    }
    if (t == 0) g_c0 = red[0] + br2[0];
}

// ---------------- mean aggregation (gather over CSR, warp per node) ----------------
// MODE 0: acc += in[row][c]
// MODE 1: acc += relu(in[row][c] + bias[c])   (fused GEMM epilogue)
// Output is tf32-rounded (it feeds a tf32 GEMM). 4-edge unroll for MLP.
template <int D, int MODE>
__global__ void agg_kernel(const float* __restrict__ in,
                           const float* __restrict__ bias,
                           float* __restrict__ out) {
    constexpr int V = D / 128;  // float4s per lane (1 or 2)
    const int warp = (blockIdx.x * blockDim.x + threadIdx.x) >> 5;
    if (warp >= NN) return;
    const int lane = threadIdx.x & 31;

    const int s = g_rowptr[warp];
    const int e = g_rowptr[warp + 1];

    float4 acc[V];
    float4 bv[V];
#pragma unroll
    for (int v = 0; v < V; v++) {
        acc[v] = make_float4(0.f, 0.f, 0.f, 0.f);
        if (MODE == 1) bv[v] = __ldg(&((const float4*)bias)[lane + v * 32]);
    }

    int j = s;
    for (; j + 3 < e; j += 4) {
        const int i0 = g_col[j];
        const int i1 = g_col[j + 1];
        const int i2 = g_col[j + 2];
        const int i3 = g_col[j + 3];
        const float4* r0 = (const float4*)&in[(size_t)i0 * D];
        const float4* r1 = (const float4*)&in[(size_t)i1 * D];
        const float4* r2 = (const float4*)&in[(size_t)i2 * D];
        const float4* r3 = (const float4*)&in[(size_t)i3 * D];
#pragma unroll
        for (int v = 0; v < V; v++) {
            float4 x0 = __ldg(&r0[lane + v * 32]);
            float4 x1 = __ldg(&r1[lane + v * 32]);
            float4 x2 = __ldg(&r2[lane + v * 32]);
            float4 x3 = __ldg(&r3[lane + v * 32]);
            if (MODE == 1) {
                x0.x = fmaxf(x0.x + bv[v].x, 0.f); x0.y = fmaxf(x0.y + bv[v].y, 0.f);
                x0.z = fmaxf(x0.z + bv[v].z, 0.f); x0.w = fmaxf(x0.w + bv[v].w, 0.f);
                x1.x = fmaxf(x1.x + bv[v].x, 0.f); x1.y = fmaxf(x1.y + bv[v].y, 0.f);
                x1.z = fmaxf(x1.z + bv[v].z, 0.f); x1.w = fmaxf(x1.w + bv[v].w, 0.f);
                x2.x = fmaxf(x2.x + bv[v].x, 0.f); x2.y = fmaxf(x2.y + bv[v].y, 0.f);
                x2.z = fmaxf(x2.z + bv[v].z, 0.f); x2.w = fmaxf(x2.w + bv[v].w, 0.f);
                x3.x = fmaxf(x3.x + bv[v].x, 0.f); x3.y = fmaxf(x3.y + bv[v].y, 0.f);
                x3.z = fmaxf(x3.z + bv[v].z, 0.f); x3.w = fmaxf(x3.w + bv[v].w, 0.f);
            }
            acc[v].x += (x0.x + x1.x) + (x2.x + x3.x);
            acc[v].y += (x0.y + x1.y) + (x2.y + x3.y);
            acc[v].z += (x0.z + x1.z) + (x2.z + x3.z);
            acc[v].w += (x0.w + x1.w) + (x2.w + x3.w);
        }
    }
    for (; j < e; j++) {
        const int i0 = g_col[j];
        const float4* r0 = (const float4*)&in[(size_t)i0 * D];
#pragma unroll
        for (int v = 0; v < V; v++) {
            float4 x = __ldg(&r0[lane + v * 32]);
            if (MODE == 1) {
                x.x = fmaxf(x.x + bv[v].x, 0.f); x.y = fmaxf(x.y + bv[v].y, 0.f);
                x.z = fmaxf(x.z + bv[v].z, 0.f); x.w = fmaxf(x.w + bv[v].w, 0.f);
            }
            acc[v].x += x.x; acc[v].y += x.y; acc[v].z += x.z; acc[v].w += x.w;
        }
    }

    const float inv = 1.f / fmaxf((float)(e - s), 1.f);
#pragma unroll
    for (int v = 0; v < V; v++) {
        float4 o;
        o.x = tf32r(acc[v].x * inv);
        o.y = tf32r(acc[v].y * inv);
        o.z = tf32r(acc[v].z * inv);
        o.w = tf32r(acc[v].w * inv);
        ((float4*)&out[(size_t)warp * D])[lane + v * 32] = o;
    }
}

// ---------------- TF32 tensor-core GEMM (double-buffered cp.async) ----------------
// C[M,256] = A[M,K] @ B[K,256]; A,B pre-rounded to tf32. M multiple of 128.
// BM=BN=128, BK=32; 8 warps (2x4), warp tile 64x32 = 4x2 m16n16k8 frags.
// (identical to the measured-good round-7 kernel)
template <int K>
__global__ __launch_bounds__(256, 2)
void gemm_tf32_kernel(const float* __restrict__ A,
                      const float* __restrict__ B,
                      float* __restrict__ C) {
    constexpr int BM = 128, BN = 128, BK = 32;
    constexpr int LDA = BK + 4;    // 36 floats = 144B (16B multiple)
    constexpr int LDB = BN + 4;    // 132 floats = 528B (16B multiple)
    constexpr int NT = K / BK;     // 4 or 8 K-tiles
    constexpr int NB = 256;        // B row stride (DH)
    __shared__ float As[2][BM][LDA];
    __shared__ float Bs[2][BK][LDB];

    const int tid = threadIdx.x;
    const int warpId = tid >> 5;
    const int warpRow = warpId >> 2;   // 0..1
    const int warpCol = warpId & 3;    // 0..3
    const int rowBase = blockIdx.y * BM;
    const int colBase = blockIdx.x * BN;

    const int aR = tid >> 3;           // 0..31 (+l*32)
    const int aC = (tid & 7) * 4;      // 0..28
    const int bR = tid >> 5;           // 0..7 (+l*8)
    const int bC = (tid & 31) * 4;     // 0..124

    auto load_tile = [&](int k0, int buf) {
#pragma unroll
        for (int l = 0; l < 4; l++) {
            int r = l * 32 + aR;
            cp_async16(&As[buf][r][aC], &A[(size_t)(rowBase + r) * K + k0 + aC]);
        }
#pragma unroll
        for (int l = 0; l < 4; l++) {
            int r = l * 8 + bR;
            cp_async16(&Bs[buf][r][bC], &B[(size_t)(k0 + r) * NB + colBase + bC]);
        }
        cp_commit();
    };

    wmma::fragment<wmma::accumulator, 16, 16, 8, float> acc[4][2];
#pragma unroll
    for (int i = 0; i < 4; i++)
#pragma unroll
        for (int j = 0; j < 2; j++) wmma::fill_fragment(acc[i][j], 0.f);

    load_tile(0, 0);

#pragma unroll
    for (int t = 0; t < NT; t++) {
        const int cur = t & 1;
        if (t + 1 < NT) {
            load_tile((t + 1) * BK, cur ^ 1);
            cp_wait1();
        } else {
            cp_wait0();
        }
        __syncthreads();

#pragma unroll
        for (int kk = 0; kk < BK; kk += 8) {
            wmma::fragment<wmma::matrix_a, 16, 16, 8, wmma::precision::tf32, wmma::row_major> a[4];
            wmma::fragment<wmma::matrix_b, 16, 16, 8, wmma::precision::tf32, wmma::row_major> b[2];
#pragma unroll
            for (int i = 0; i < 4; i++)
                wmma::load_matrix_sync(a[i], &As[cur][warpRow * 64 + i * 16][kk], LDA);
#pragma unroll
            for (int j = 0; j < 2; j++)
                wmma::load_matrix_sync(b[j], &Bs[cur][kk][warpCol * 32 + j * 16], LDB);
#pragma unroll
            for (int i = 0; i < 4; i++)
#pragma unroll
                for (int j = 0; j < 2; j++)
                    wmma::mma_sync(acc[i][j], a[i], b[j], acc[i][j]);
        }
        __syncthreads();
    }

#pragma unroll
    for (int i = 0; i < 4; i++)
#pragma unroll
        for (int j = 0; j < 2; j++) {
            int r = rowBase + warpRow * 64 + i * 16;
            int c = colBase + warpCol * 32 + j * 16;
            wmma::store_matrix_sync(&C[(size_t)r * NB + c], acc[i][j], NB, wmma::mem_row_major);
        }
}

// ---------------- fused readout: per-node dot of relu(h2+b2) with wc ----------------
// warp per node row; coalesced 1KB row read; one atomic per row into graph sums.
__global__ void dot_readout_kernel(const int* __restrict__ gid,
                                   const float* __restrict__ b2, int n) {
    const int row = (blockIdx.x * blockDim.x + threadIdx.x) >> 5;
    if (row >= n) return;
    const int lane = threadIdx.x & 31;
    const float4* h2 = (const float4*)&g_h2[(size_t)row * DH];

    float d = 0.f;
#pragma unroll
    for (int v = 0; v < 2; v++) {
        const int c = lane + v * 32;
        float4 x  = __ldg(&h2[c]);
        float4 bv = __ldg(&((const float4*)b2)[c]);
        float4 wv = *(const float4*)&g_wc[c * 4];
        d += fmaxf(x.x + bv.x, 0.f) * wv.x
           + fmaxf(x.y + bv.y, 0.f) * wv.y
           + fmaxf(x.z + bv.z, 0.f) * wv.z
           + fmaxf(x.w + bv.w, 0.f) * wv.w;
    }
#pragma unroll
    for (int off = 16; off > 0; off >>= 1)
        d += __shfl_xor_sync(0xffffffffu, d, off);
    if (lane == 0) atomicAdd(&g_gsum[gid[row]], d);
}

// ---------------- finalize: out[g] = gsum[g]/cnt_g + c0 ----------------
__global__ void finalize_kernel(const int* __restrict__ gid, int n, float* __restrict__ out) {
    const int g = threadIdx.x;  // 256
    int lo = 0, hi = n;
    while (lo < hi) { int m = (lo + hi) >> 1; if (gid[m] < g) lo = m + 1; else hi = m; }
    const int a = lo;
    hi = n;
    while (lo < hi) { int m = (lo + hi) >> 1; if (gid[m] <= g) lo = m + 1; else hi = m; }
    const float cnt = (float)(lo - a);
    out[g] = g_gsum[g] / fmaxf(cnt, 1.f) + g_c0;
}

// ---------------- launch ----------------
extern "C" void kernel_launch(void* const* d_in, const int* in_sizes, int n_in,
                              void* d_out, int out_size) {
    const float* h   = (const float*)d_in[0];
    const int*   src = (const int*)d_in[1];
    const int*   dst = (const int*)d_in[2];
    const int*   gid = (const int*)d_in[3];
    const float* W1  = (const float*)d_in[4];
    const float* b1  = (const float*)d_in[5];
    const float* W2  = (const float*)d_in[6];
    const float* b2  = (const float*)d_in[7];
    const float* Wr1 = (const float*)d_in[8];
    const float* br1 = (const float*)d_in[9];
    const float* Wr2 = (const float*)d_in[10];
    const float* br2 = (const float*)d_in[11];
    float* out = (float*)d_out;

    const int N = in_sizes[0] / DIN;   // 50000
    const int E = in_sizes[1];         // 800000

    float *pa1, *ph1, *pa2, *ph2, *pw1, *pw2;
    cudaGetSymbolAddress((void**)&pa1, g_a1);
    cudaGetSymbolAddress((void**)&ph1, g_h1);
    cudaGetSymbolAddress((void**)&pa2, g_a2);
    cudaGetSymbolAddress((void**)&ph2, g_h2);
    cudaGetSymbolAddress((void**)&pw1, g_w1r);
    cudaGetSymbolAddress((void**)&pw2, g_w2r);

    // 1) CSR build + weight prep + head collapse (also zeroes g_gsum)
    zero_deg_kernel<<<(N + 255) / 256, 256>>>(N);
    hist_kernel<<<(E + 255) / 256, 256>>>(dst, E);
    wc_kernel<<<1, 256>>>(Wr1, br1, Wr2, br2);
    round_w_kernel<<<(DIN * DH / 4 + 255) / 256, 256>>>((const float4*)W1, (float4*)pw1, DIN * DH / 4);
    round_w_kernel<<<(DH * DH / 4 + 255) / 256, 256>>>((const float4*)W2, (float4*)pw2, DH * DH / 4);
    scan_kernel<<<1, 1024>>>(N);
    fill_kernel<<<(E + 255) / 256, 256>>>(src, dst, E);

    // 2) layer 1: mean-agg then tf32 GEMM  [N,128]@[128,256] (raw C out)
    agg_kernel<DIN, 0><<<(NN * 32 + 255) / 256, 256>>>(h, nullptr, pa1);
    {
        dim3 grid(DH / 128, NN_PAD / 128);
        gemm_tf32_kernel<DIN><<<grid, 256>>>(pa1, pw1, ph1);
    }

    // 3) layer 2: mean-agg (fused relu(x+b1)) then tf32 GEMM  [N,256]@[256,256]
    agg_kernel<DH, 1><<<(NN * 32 + 255) / 256, 256>>>(ph1, b1, pa2);
    {
        dim3 grid(DH / 128, NN_PAD / 128);
        gemm_tf32_kernel<DH><<<grid, 256>>>(pa2, pw2, ph2);
    }

    // 4) fused readout (relu(x+b2)·wc per node -> graph sums) + finalize
    dot_readout_kernel<<<(NN * 32 + 255) / 256, 256>>>(gid, b2, N);
    finalize_kernel<<<1, 256>>>(gid, N, out);
}

// round 13
// speedup vs baseline: 2.2055x; 1.5551x over previous
#include <cstdint>
#include <cuda_runtime.h>
#include <cuda_fp16.h>
#include <mma.h>

using namespace nvcuda;

// ---------------- problem constants (fixed shapes) ----------------
#define NN 50000      // nodes
#define NN_PAD 50048  // padded to 391*128 for wmma tiles
#define NE 800000     // edges
#define DIN 128       // input feature dim
#define DH  256       // hidden dim (H1)
#define H2D 128       // readout hidden dim
#define NG  256       // num graphs

// ---------------- device scratch (static, allocation-free) ----------------
__device__ int    g_deg[NN];
__device__ int    g_rowptr[NN + 1];
__device__ int    g_cursor[NN];
__device__ int    g_col[NE];
__device__ __align__(128) __half g_a1[(size_t)NN_PAD * DIN];  // mean-agg of h (fp16)
__device__ __align__(128) __half g_h1[(size_t)NN_PAD * DH];   // relu(a1@W1+b1) (fp16)
__device__ __align__(128) __half g_a2[(size_t)NN_PAD * DH];   // mean-agg of h1 (fp16)
__device__ __align__(128) __half g_h2[(size_t)NN_PAD * DH];   // relu(a2@W2+b2) (fp16)
__device__ __align__(128) __half g_w1h[DIN * DH];             // fp16 W1
__device__ __align__(128) __half g_w2h[DH * DH];              // fp16 W2
__device__ float  g_wc[DH];    // Wr1 @ Wr2  [256]
__device__ float  g_gsum[NG];  // per-graph partial dot sums
__device__ float  g_c0;        // br1.Wr2 + br2

// ---------------- helpers ----------------
__device__ __forceinline__ void cp_async16(void* smem, const void* gmem) {
    unsigned int s = (unsigned int)__cvta_generic_to_shared(smem);
    asm volatile("cp.async.cg.shared.global [%0], [%1], 16;\n" :: "r"(s), "l"(gmem));
}
__device__ __forceinline__ void cp_commit() {
    asm volatile("cp.async.commit_group;\n");
}
__device__ __forceinline__ void cp_wait1() {
    asm volatile("cp.async.wait_group 1;\n");
}
__device__ __forceinline__ void cp_wait0() {
    asm volatile("cp.async.wait_group 0;\n");
}

// ---------------- CSR build ----------------
__global__ void zero_deg_kernel(int n) {
    int i = blockIdx.x * blockDim.x + threadIdx.x;
    if (i < n) g_deg[i] = 0;
}

__global__ void hist_kernel(const int* __restrict__ dst, int e) {
    int i = blockIdx.x * blockDim.x + threadIdx.x;
    if (i < e) atomicAdd(&g_deg[dst[i]], 1);
}

__global__ void scan_kernel(int n) {
    __shared__ int sums[1024];
    const int t = threadIdx.x;
    const int C = (n + 1023) / 1024;
    const int start = t * C;
    const int end = min(start + C, n);

    int local = 0;
    for (int i = start; i < end; i++) local += g_deg[i];
    sums[t] = local;
    __syncthreads();

    for (int off = 1; off < 1024; off <<= 1) {
        int v = (t >= off) ? sums[t - off] : 0;
        __syncthreads();
        sums[t] += v;
        __syncthreads();
    }

    int run = sums[t] - local;
    for (int i = start; i < end; i++) {
        g_rowptr[i] = run;
        g_cursor[i] = run;
        run += g_deg[i];
    }
    if (start < n && end == n) g_rowptr[n] = run;
}

__global__ void fill_kernel(const int* __restrict__ src, const int* __restrict__ dst, int e) {
    int i = blockIdx.x * blockDim.x + threadIdx.x;
    if (i < e) {
        int pos = atomicAdd(&g_cursor[dst[i]], 1);
        g_col[pos] = src[i];
    }
}

// ---------------- weight fp32 -> fp16 ----------------
__global__ void w_to_h_kernel(const float4* __restrict__ w, uint2* __restrict__ out, int n4) {
    int i = blockIdx.x * blockDim.x + threadIdx.x;
    if (i < n4) {
        float4 v = w[i];
        __half2 lo = __floats2half2_rn(v.x, v.y);
        __half2 hi = __floats2half2_rn(v.z, v.w);
        uint2 o;
        o.x = *(unsigned int*)&lo;
        o.y = *(unsigned int*)&hi;
        out[i] = o;
    }
}

// ---------------- head collapse: wc = Wr1@Wr2, c0 = br1.Wr2 + br2 ----------------
// Also zeroes g_gsum (must run before dot_readout).
__global__ void wc_kernel(const float* __restrict__ Wr1, const float* __restrict__ br1,
                          const float* __restrict__ Wr2, const float* __restrict__ br2) {
    const int t = threadIdx.x;  // 256
    float acc = 0.f;
    for (int j = 0; j < H2D; j++) acc += Wr1[t * H2D + j] * Wr2[j];
    g_wc[t] = acc;
    g_gsum[t] = 0.f;
    __shared__ float red[H2D];
    if (t < H2D) red[t] = br1[t] * Wr2[t];
    __syncthreads();
    for (int s = H2D / 2; s > 0; s >>= 1) {
        if (t < s) red[t] += red[t + s];
        __syncthreads();
    }
    if (t == 0) g_c0 = red[0] + br2[0];
}

// ---------------- agg layer 1: fp32 input rows -> mean -> fp16 out ----------------
// warp per node; lane owns float4 chunk `lane` of the 128-float row.
__global__ void agg1_kernel(const float* __restrict__ in, __half* __restrict__ out) {
    const int node = (blockIdx.x * blockDim.x + threadIdx.x) >> 5;
    if (node >= NN) return;
    const int lane = threadIdx.x & 31;

    const int s = g_rowptr[node];
    const int e = g_rowptr[node + 1];
    const float4* base = (const float4*)in;

    float4 acc = make_float4(0.f, 0.f, 0.f, 0.f);
    int j = s;
    for (; j + 3 < e; j += 4) {
        const int i0 = g_col[j], i1 = g_col[j + 1], i2 = g_col[j + 2], i3 = g_col[j + 3];
        float4 x0 = __ldg(&base[(size_t)i0 * 32 + lane]);
        float4 x1 = __ldg(&base[(size_t)i1 * 32 + lane]);
        float4 x2 = __ldg(&base[(size_t)i2 * 32 + lane]);
        float4 x3 = __ldg(&base[(size_t)i3 * 32 + lane]);
        acc.x += (x0.x + x1.x) + (x2.x + x3.x);
        acc.y += (x0.y + x1.y) + (x2.y + x3.y);
        acc.z += (x0.z + x1.z) + (x2.z + x3.z);
        acc.w += (x0.w + x1.w) + (x2.w + x3.w);
    }
    for (; j < e; j++) {
        float4 x = __ldg(&base[(size_t)g_col[j] * 32 + lane]);
        acc.x += x.x; acc.y += x.y; acc.z += x.z; acc.w += x.w;
    }

    const float inv = 1.f / fmaxf((float)(e - s), 1.f);
    __half2 lo = __floats2half2_rn(acc.x * inv, acc.y * inv);
    __half2 hi = __floats2half2_rn(acc.z * inv, acc.w * inv);
    uint2 o;
    o.x = *(unsigned int*)&lo;
    o.y = *(unsigned int*)&hi;
    ((uint2*)&out[(size_t)node * DIN])[lane] = o;
}

// ---------------- agg layer 2: fp16 input rows (256 halves) -> mean -> fp16 ----------------
// warp per node; lane owns 8-half chunk `lane` of the 512B row.
__global__ void agg2_kernel(const __half* __restrict__ in, __half* __restrict__ out) {
    const int node = (blockIdx.x * blockDim.x + threadIdx.x) >> 5;
    if (node >= NN) return;
    const int lane = threadIdx.x & 31;

    const int s = g_rowptr[node];
    const int e = g_rowptr[node + 1];
    const uint4* base = (const uint4*)in;  // 8 halves per uint4; row = 32 uint4

    float2 acc[4];
#pragma unroll
    for (int k = 0; k < 4; k++) acc[k] = make_float2(0.f, 0.f);

    auto addv = [&](uint4 v) {
        const __half2* hp = (const __half2*)&v;
#pragma unroll
        for (int k = 0; k < 4; k++) {
            float2 f = __half22float2(hp[k]);
            acc[k].x += f.x; acc[k].y += f.y;
        }
    };

    int j = s;
    for (; j + 3 < e; j += 4) {
        const int i0 = g_col[j], i1 = g_col[j + 1], i2 = g_col[j + 2], i3 = g_col[j + 3];
        uint4 x0 = __ldg(&base[(size_t)i0 * 32 + lane]);
        uint4 x1 = __ldg(&base[(size_t)i1 * 32 + lane]);
        uint4 x2 = __ldg(&base[(size_t)i2 * 32 + lane]);
        uint4 x3 = __ldg(&base[(size_t)i3 * 32 + lane]);
        addv(x0); addv(x1); addv(x2); addv(x3);
    }
    for (; j < e; j++) {
        addv(__ldg(&base[(size_t)g_col[j] * 32 + lane]));
    }

    const float inv = 1.f / fmaxf((float)(e - s), 1.f);
    uint4 o;
    __half2* op = (__half2*)&o;
#pragma unroll
    for (int k = 0; k < 4; k++)
        op[k] = __floats2half2_rn(acc[k].x * inv, acc[k].y * inv);
    ((uint4*)&out[(size_t)node * DH])[lane] = o;
}

// ---------------- fp16 tensor-core GEMM (double-buffered cp.async) ----------------
// C[M,256] = relu(A[M,K] @ B[K,256] + bias), all A/B/C fp16, fp32 accumulate.
// BM=BN=128, BK=32; 8 warps (2x4), warp tile 64x32 = 4x2 m16n16k16 frags.
// Epilogue: per-warp smem fragment staging -> bias+relu -> fp16 stores.
template <int K>
__global__ __launch_bounds__(256, 2)
void gemm_fp16_kernel(const __half* __restrict__ A,
                      const __half* __restrict__ B,
                      __half* __restrict__ C,
                      const float* __restrict__ bias) {
    constexpr int BM = 128, BN = 128, BK = 32;
    constexpr int LDA = BK + 8;    // 40 halves = 80B stride (16B multiple)
    constexpr int LDB = BN + 8;    // 136 halves = 272B stride (16B multiple)
    constexpr int NT = K / BK;     // 4 or 8 K-tiles
    constexpr int NB = 256;        // B/C row stride (DH)
    __shared__ __half As[2][BM][LDA];            // 20480 B
    __shared__ __half Bs[2][BK][LDB];            // 17408 B
    __shared__ __align__(16) float ws[8][16][20]; // 10240 B per-warp epilogue scratch

    const int tid = threadIdx.x;
    const int warpId = tid >> 5;
    const int lane = tid & 31;
    const int warpRow = warpId >> 2;   // 0..1
    const int warpCol = warpId & 3;    // 0..3
    const int rowBase = blockIdx.y * BM;
    const int colBase = blockIdx.x * BN;

    // A tile: 128 rows x 32 halves = 4 chunks/row of 8 halves; 512 chunks, 2/thread
    // B tile: 32 rows x 128 halves = 16 chunks/row; 512 chunks, 2/thread
    auto load_tile = [&](int k0, int buf) {
#pragma unroll
        for (int l = 0; l < 2; l++) {
            int lin = tid + l * 256;
            int r = lin >> 2;            // 0..127
            int c8 = (lin & 3) * 8;      // 0,8,16,24
            cp_async16(&As[buf][r][c8], &A[(size_t)(rowBase + r) * K + k0 + c8]);
        }
#pragma unroll
        for (int l = 0; l < 2; l++) {
            int lin = tid + l * 256;
            int r = lin >> 4;            // 0..31
            int c8 = (lin & 15) * 8;     // 0..120
            cp_async16(&Bs[buf][r][c8], &B[(size_t)(k0 + r) * NB + colBase + c8]);
        }
        cp_commit();
    };

    wmma::fragment<wmma::accumulator, 16, 16, 16, float> acc[4][2];
#pragma unroll
    for (int i = 0; i < 4; i++)
#pragma unroll
        for (int j = 0; j < 2; j++) wmma::fill_fragment(acc[i][j], 0.f);

    load_tile(0, 0);

#pragma unroll
    for (int t = 0; t < NT; t++) {
        const int cur = t & 1;
        if (t + 1 < NT) {
            load_tile((t + 1) * BK, cur ^ 1);
            cp_wait1();
        } else {
            cp_wait0();
        }
        __syncthreads();

#pragma unroll
        for (int kk = 0; kk < BK; kk += 16) {
            wmma::fragment<wmma::matrix_a, 16, 16, 16, __half, wmma::row_major> a[4];
            wmma::fragment<wmma::matrix_b, 16, 16, 16, __half, wmma::row_major> b[2];
#pragma unroll
            for (int i = 0; i < 4; i++)
                wmma::load_matrix_sync(a[i], &As[cur][warpRow * 64 + i * 16][kk], LDA);
#pragma unroll
            for (int j = 0; j < 2; j++)
                wmma::load_matrix_sync(b[j], &Bs[cur][kk][warpCol * 32 + j * 16], LDB);
#pragma unroll
            for (int i = 0; i < 4; i++)
#pragma unroll
                for (int j = 0; j < 2; j++)
                    wmma::mma_sync(acc[i][j], a[i], b[j], acc[i][j]);
        }
        __syncthreads();
    }

    // ---- epilogue: per-warp fragment staging; bias+relu; fp16 stores ----
    // lane -> (fragment row fr = lane>>1, 8-col chunk fc0 = (lane&1)*8)
    const int fr = lane >> 1;
    const int fc0 = (lane & 1) * 8;
#pragma unroll
    for (int i = 0; i < 4; i++) {
#pragma unroll
        for (int j = 0; j < 2; j++) {
            wmma::store_matrix_sync(&ws[warpId][0][0], acc[i][j], 20, wmma::mem_row_major);
            __syncwarp();
            float4 v0 = *(const float4*)&ws[warpId][fr][fc0];
            float4 v1 = *(const float4*)&ws[warpId][fr][fc0 + 4];
            __syncwarp();
            const int grow = rowBase + warpRow * 64 + i * 16 + fr;
            const int gcol = colBase + warpCol * 32 + j * 16 + fc0;
            float4 b0 = *(const float4*)&bias[gcol];
            float4 b1 = *(const float4*)&bias[gcol + 4];
            __half2 h0 = __floats2half2_rn(fmaxf(v0.x + b0.x, 0.f), fmaxf(v0.y + b0.y, 0.f));
            __half2 h1 = __floats2half2_rn(fmaxf(v0.z + b0.z, 0.f), fmaxf(v0.w + b0.w, 0.f));
            __half2 h2 = __floats2half2_rn(fmaxf(v1.x + b1.x, 0.f), fmaxf(v1.y + b1.y, 0.f));
            __half2 h3 = __floats2half2_rn(fmaxf(v1.z + b1.z, 0.f), fmaxf(v1.w + b1.w, 0.f));
            uint4 o;
            o.x = *(unsigned int*)&h0;
            o.y = *(unsigned int*)&h1;
            o.z = *(unsigned int*)&h2;
            o.w = *(unsigned int*)&h3;
            *(uint4*)&C[(size_t)grow * NB + gcol] = o;
        }
    }
}

// ---------------- fused readout: per-node dot of h2 (already relu'd) with wc ----------------
__global__ void dot_readout_kernel(const int* __restrict__ gid, int n) {
    const int row = (blockIdx.x * blockDim.x + threadIdx.x) >> 5;
    if (row >= n) return;
    const int lane = threadIdx.x & 31;

    uint4 hv = __ldg((const uint4*)&g_h2[(size_t)row * DH + lane * 8]);
    const __half2* hp = (const __half2*)&hv;
    float4 w0 = *(const float4*)&g_wc[lane * 8];
    float4 w1 = *(const float4*)&g_wc[lane * 8 + 4];

    float2 f0 = __half22float2(hp[0]);
    float2 f1 = __half22float2(hp[1]);
    float2 f2 = __half22float2(hp[2]);
    float2 f3 = __half22float2(hp[3]);
    float d = f0.x * w0.x + f0.y * w0.y + f1.x * w0.z + f1.y * w0.w
            + f2.x * w1.x + f2.y * w1.y + f3.x * w1.z + f3.y * w1.w;

#pragma unroll
    for (int off = 16; off > 0; off >>= 1)
        d += __shfl_xor_sync(0xffffffffu, d, off);
    if (lane == 0) atomicAdd(&g_gsum[gid[row]], d);
}

// ---------------- finalize: out[g] = gsum[g]/cnt_g + c0 ----------------
__global__ void finalize_kernel(const int* __restrict__ gid, int n, float* __restrict__ out) {
    const int g = threadIdx.x;  // 256
    int lo = 0, hi = n;
    while (lo < hi) { int m = (lo + hi) >> 1; if (gid[m] < g) lo = m + 1; else hi = m; }
    const int a = lo;
    hi = n;
    while (lo < hi) { int m = (lo + hi) >> 1; if (gid[m] <= g) lo = m + 1; else hi = m; }
    const float cnt = (float)(lo - a);
    out[g] = g_gsum[g] / fmaxf(cnt, 1.f) + g_c0;
}

// ---------------- launch ----------------
extern "C" void kernel_launch(void* const* d_in, const int* in_sizes, int n_in,
                              void* d_out, int out_size) {
    const float* h   = (const float*)d_in[0];
    const int*   src = (const int*)d_in[1];
    const int*   dst = (const int*)d_in[2];
    const int*   gid = (const int*)d_in[3];
    const float* W1  = (const float*)d_in[4];
    const float* b1  = (const float*)d_in[5];
    const float* W2  = (const float*)d_in[6];
    const float* b2  = (const float*)d_in[7];
    const float* Wr1 = (const float*)d_in[8];
    const float* br1 = (const float*)d_in[9];
    const float* Wr2 = (const float*)d_in[10];
    const float* br2 = (const float*)d_in[11];
    float* out = (float*)d_out;

    const int N = in_sizes[0] / DIN;   // 50000
    const int E = in_sizes[1];         // 800000

    __half *pa1, *ph1, *pa2, *ph2, *pw1, *pw2;
    cudaGetSymbolAddress((void**)&pa1, g_a1);
    cudaGetSymbolAddress((void**)&ph1, g_h1);
    cudaGetSymbolAddress((void**)&pa2, g_a2);
    cudaGetSymbolAddress((void**)&ph2, g_h2);
    cudaGetSymbolAddress((void**)&pw1, g_w1h);
    cudaGetSymbolAddress((void**)&pw2, g_w2h);

    // 1) CSR build + weight fp16 conversion + head collapse (zeroes g_gsum)
    zero_deg_kernel<<<(N + 255) / 256, 256>>>(N);
    hist_kernel<<<(E + 255) / 256, 256>>>(dst, E);
    wc_kernel<<<1, 256>>>(Wr1, br1, Wr2, br2);
    w_to_h_kernel<<<(DIN * DH / 4 + 255) / 256, 256>>>((const float4*)W1, (uint2*)pw1, DIN * DH / 4);
    w_to_h_kernel<<<(DH * DH / 4 + 255) / 256, 256>>>((const float4*)W2, (uint2*)pw2, DH * DH / 4);
    scan_kernel<<<1, 1024>>>(N);
    fill_kernel<<<(E + 255) / 256, 256>>>(src, dst, E);

    // 2) layer 1: mean-agg (fp32 in, fp16 out) -> fp16 GEMM + fused relu+b1
    agg1_kernel<<<(NN * 32 + 255) / 256, 256>>>(h, pa1);
    {
        dim3 grid(DH / 128, NN_PAD / 128);
        gemm_fp16_kernel<DIN><<<grid, 256>>>(pa1, pw1, ph1, b1);
    }

    // 3) layer 2: pure mean-agg (fp16) -> fp16 GEMM + fused relu+b2
    agg2_kernel<<<(NN * 32 + 255) / 256, 256>>>(ph1, pa2);
    {
        dim3 grid(DH / 128, NN_PAD / 128);
        gemm_fp16_kernel<DH><<<grid, 256>>>(pa2, pw2, ph2, b2);
    }

    // 4) fused readout (h2·wc per node -> graph sums) + finalize
    dot_readout_kernel<<<(NN * 32 + 255) / 256, 256>>>(gid, N);
    finalize_kernel<<<1, 256>>>(gid, N, out);
}